// round 4
// baseline (speedup 1.0000x reference)
#include <cuda_runtime.h>
#include <float.h>

#define BB 4096
#define NN 2048
#define NPAIR 3
#define ROW_THREADS 256
#define NBLOCKS (BB * NPAIR)

// Per-(pair,row) weighted contributions + completion ticket.
// Final sum is fixed-order -> deterministic output regardless of which CTA is last.
__device__ float g_partials[NPAIR * BB];
__device__ unsigned int g_count = 0;

__global__ __launch_bounds__(ROW_THREADS)
void wnrmse_kernel(const float* __restrict__ o1, const float* __restrict__ t1,
                   const float* __restrict__ o2, const float* __restrict__ t2,
                   const float* __restrict__ o3, const float* __restrict__ t3,
                   float* __restrict__ out) {
    const int b = blockIdx.x;   // batch row
    const int p = blockIdx.y;   // pair index
    const int tid = threadIdx.x;
    const int w = tid >> 5, l = tid & 31;

    const float* o = (p == 0) ? o1 : ((p == 1) ? o2 : o3);
    const float* t = (p == 0) ? t1 : ((p == 1) ? t2 : t3);

    const float4* __restrict__ o4 = reinterpret_cast<const float4*>(o + (size_t)b * NN);
    const float4* __restrict__ t4 = reinterpret_cast<const float4*>(t + (size_t)b * NN);

    // 2048 floats = 512 float4; 256 threads -> 2 float4 each. Front-batch all 4 loads.
    float4 ov0 = o4[tid];
    float4 tv0 = t4[tid];
    float4 ov1 = o4[tid + ROW_THREADS];
    float4 tv1 = t4[tid + ROW_THREADS];

    float ssq = 0.0f, tmax = -FLT_MAX, tmin = FLT_MAX;
    {
        float d;
        d = ov0.x - tv0.x; ssq = fmaf(d, d, ssq); tmax = fmaxf(tmax, tv0.x); tmin = fminf(tmin, tv0.x);
        d = ov0.y - tv0.y; ssq = fmaf(d, d, ssq); tmax = fmaxf(tmax, tv0.y); tmin = fminf(tmin, tv0.y);
        d = ov0.z - tv0.z; ssq = fmaf(d, d, ssq); tmax = fmaxf(tmax, tv0.z); tmin = fminf(tmin, tv0.z);
        d = ov0.w - tv0.w; ssq = fmaf(d, d, ssq); tmax = fmaxf(tmax, tv0.w); tmin = fminf(tmin, tv0.w);
        d = ov1.x - tv1.x; ssq = fmaf(d, d, ssq); tmax = fmaxf(tmax, tv1.x); tmin = fminf(tmin, tv1.x);
        d = ov1.y - tv1.y; ssq = fmaf(d, d, ssq); tmax = fmaxf(tmax, tv1.y); tmin = fminf(tmin, tv1.y);
        d = ov1.z - tv1.z; ssq = fmaf(d, d, ssq); tmax = fmaxf(tmax, tv1.z); tmin = fminf(tmin, tv1.z);
        d = ov1.w - tv1.w; ssq = fmaf(d, d, ssq); tmax = fmaxf(tmax, tv1.w); tmin = fminf(tmin, tv1.w);
    }

    // Intra-warp reduce
    #pragma unroll
    for (int s = 16; s > 0; s >>= 1) {
        ssq  += __shfl_xor_sync(0xFFFFFFFFu, ssq,  s);
        tmax  = fmaxf(tmax, __shfl_xor_sync(0xFFFFFFFFu, tmax, s));
        tmin  = fminf(tmin, __shfl_xor_sync(0xFFFFFFFFu, tmin, s));
    }

    // Cross-warp reduce (8 warps)
    __shared__ float s_ssq[8], s_max[8], s_min[8];
    __shared__ unsigned int s_ticket;
    if (l == 0) { s_ssq[w] = ssq; s_max[w] = tmax; s_min[w] = tmin; }
    __syncthreads();

    if (tid == 0) {
        float a = s_ssq[0], mx = s_max[0], mn = s_min[0];
        #pragma unroll
        for (int i = 1; i < 8; i++) {
            a += s_ssq[i];
            mx = fmaxf(mx, s_max[i]);
            mn = fminf(mn, s_min[i]);
        }
        const float wgt = (p == 0) ? 0.5f : 0.25f;
        g_partials[p * BB + b] = wgt * sqrtf(a * (1.0f / NN)) / (mx - mn);

        // Release-atomic ticket: orders the partial store before the increment
        // WITHOUT a fence instruction (no CCTL.IVALL / L1 flush).
        unsigned int ticket;
        asm volatile("atom.release.gpu.global.add.u32 %0, [%1], %2;"
                     : "=r"(ticket) : "l"(&g_count), "r"(1u) : "memory");
        s_ticket = ticket;
    }
    __syncthreads();

    // Last CTA performs the fixed-order final reduction (L2-hot, ~1us).
    if (s_ticket == (unsigned)(NBLOCKS - 1)) {
        __threadfence();   // single acquire fence in the whole grid: cost ~0

        // 12288 floats = 3072 float4; 256 threads -> 12 float4 each.
        const float4* __restrict__ p4 = reinterpret_cast<const float4*>(g_partials);
        float s = 0.0f;
        #pragma unroll
        for (int i = 0; i < 12; i++) {
            float4 v = p4[tid + i * ROW_THREADS];
            s += (v.x + v.y) + (v.z + v.w);
        }

        #pragma unroll
        for (int sh = 16; sh > 0; sh >>= 1)
            s += __shfl_xor_sync(0xFFFFFFFFu, s, sh);

        __shared__ float s_fin[8];
        if (l == 0) s_fin[w] = s;
        __syncthreads();
        if (tid == 0) {
            float a = s_fin[0];
            #pragma unroll
            for (int i = 1; i < 8; i++) a += s_fin[i];
            out[0] = a * (1.0f / BB);
            g_count = 0;   // reset for next graph replay
        }
    }
}

extern "C" void kernel_launch(void* const* d_in, const int* in_sizes, int n_in,
                              void* d_out, int out_size) {
    const float* o1 = (const float*)d_in[0];
    const float* t1 = (const float*)d_in[1];
    const float* o2 = (const float*)d_in[2];
    const float* t2 = (const float*)d_in[3];
    const float* o3 = (const float*)d_in[4];
    const float* t3 = (const float*)d_in[5];
    float* out = (float*)d_out;

    dim3 grid(BB, NPAIR);
    wnrmse_kernel<<<grid, ROW_THREADS>>>(o1, t1, o2, t2, o3, t3, out);
}

// round 5
// speedup vs baseline: 1.0652x; 1.0652x over previous
#include <cuda_runtime.h>
#include <float.h>

#define BB 4096
#define NN 2048
#define NPAIR 3
#define ROW_THREADS 256
#define RED_THREADS 1024

// Per-(pair,row) weighted contributions. Deterministic fixed-order final sum.
__device__ float g_partials[NPAIR * BB];

__global__ __launch_bounds__(ROW_THREADS)
void wnrmse_row_kernel(const float* __restrict__ o1, const float* __restrict__ t1,
                       const float* __restrict__ o2, const float* __restrict__ t2,
                       const float* __restrict__ o3, const float* __restrict__ t3) {
    const int b = blockIdx.x;   // batch row
    const int p = blockIdx.y;   // pair index
    const int tid = threadIdx.x;

    const float* o = (p == 0) ? o1 : ((p == 1) ? o2 : o3);
    const float* t = (p == 0) ? t1 : ((p == 1) ? t2 : t3);

    const float4* __restrict__ o4 = reinterpret_cast<const float4*>(o + (size_t)b * NN);
    const float4* __restrict__ t4 = reinterpret_cast<const float4*>(t + (size_t)b * NN);

    // 2048 floats = 512 float4; 256 threads -> 2 float4 each. Front-batch all 4 loads.
    float4 ov0 = o4[tid];
    float4 tv0 = t4[tid];
    float4 ov1 = o4[tid + ROW_THREADS];
    float4 tv1 = t4[tid + ROW_THREADS];

    float ssq = 0.0f, tmax = -FLT_MAX, tmin = FLT_MAX;
    {
        float d;
        d = ov0.x - tv0.x; ssq = fmaf(d, d, ssq); tmax = fmaxf(tmax, tv0.x); tmin = fminf(tmin, tv0.x);
        d = ov0.y - tv0.y; ssq = fmaf(d, d, ssq); tmax = fmaxf(tmax, tv0.y); tmin = fminf(tmin, tv0.y);
        d = ov0.z - tv0.z; ssq = fmaf(d, d, ssq); tmax = fmaxf(tmax, tv0.z); tmin = fminf(tmin, tv0.z);
        d = ov0.w - tv0.w; ssq = fmaf(d, d, ssq); tmax = fmaxf(tmax, tv0.w); tmin = fminf(tmin, tv0.w);
        d = ov1.x - tv1.x; ssq = fmaf(d, d, ssq); tmax = fmaxf(tmax, tv1.x); tmin = fminf(tmin, tv1.x);
        d = ov1.y - tv1.y; ssq = fmaf(d, d, ssq); tmax = fmaxf(tmax, tv1.y); tmin = fminf(tmin, tv1.y);
        d = ov1.z - tv1.z; ssq = fmaf(d, d, ssq); tmax = fmaxf(tmax, tv1.z); tmin = fminf(tmin, tv1.z);
        d = ov1.w - tv1.w; ssq = fmaf(d, d, ssq); tmax = fmaxf(tmax, tv1.w); tmin = fminf(tmin, tv1.w);
    }

    // Intra-warp reduce
    #pragma unroll
    for (int s = 16; s > 0; s >>= 1) {
        ssq  += __shfl_xor_sync(0xFFFFFFFFu, ssq,  s);
        tmax  = fmaxf(tmax, __shfl_xor_sync(0xFFFFFFFFu, tmax, s));
        tmin  = fminf(tmin, __shfl_xor_sync(0xFFFFFFFFu, tmin, s));
    }

    // Cross-warp reduce (8 warps)
    __shared__ float s_ssq[8], s_max[8], s_min[8];
    const int w = tid >> 5, l = tid & 31;
    if (l == 0) { s_ssq[w] = ssq; s_max[w] = tmax; s_min[w] = tmin; }
    __syncthreads();

    if (tid == 0) {
        float a = s_ssq[0], mx = s_max[0], mn = s_min[0];
        #pragma unroll
        for (int i = 1; i < 8; i++) {
            a += s_ssq[i];
            mx = fmaxf(mx, s_max[i]);
            mn = fminf(mn, s_min[i]);
        }
        const float wgt = (p == 0) ? 0.5f : 0.25f;
        g_partials[p * BB + b] = wgt * sqrtf(a * (1.0f / NN)) / (mx - mn);
    }
}

// Fast tail: 12288 floats = 3072 float4; 1024 threads -> 3 float4 each,
// front-batched (MLP=3), all L2-hot from the preceding kernel.
__global__ __launch_bounds__(RED_THREADS)
void wnrmse_reduce_kernel(float* __restrict__ out) {
    const int tid = threadIdx.x;
    const float4* __restrict__ p4 = reinterpret_cast<const float4*>(g_partials);

    float4 v0 = p4[tid];
    float4 v1 = p4[tid + RED_THREADS];
    float4 v2 = p4[tid + 2 * RED_THREADS];

    float s = ((v0.x + v0.y) + (v0.z + v0.w))
            + ((v1.x + v1.y) + (v1.z + v1.w))
            + ((v2.x + v2.y) + (v2.z + v2.w));

    #pragma unroll
    for (int sh = 16; sh > 0; sh >>= 1)
        s += __shfl_xor_sync(0xFFFFFFFFu, s, sh);

    __shared__ float s_part[32];
    const int w = tid >> 5, l = tid & 31;
    if (l == 0) s_part[w] = s;
    __syncthreads();
    if (w == 0) {
        float a = s_part[l];   // exactly 32 warps
        #pragma unroll
        for (int sh = 16; sh > 0; sh >>= 1)
            a += __shfl_xor_sync(0xFFFFFFFFu, a, sh);
        if (l == 0) out[0] = a * (1.0f / BB);
    }
}

extern "C" void kernel_launch(void* const* d_in, const int* in_sizes, int n_in,
                              void* d_out, int out_size) {
    const float* o1 = (const float*)d_in[0];
    const float* t1 = (const float*)d_in[1];
    const float* o2 = (const float*)d_in[2];
    const float* t2 = (const float*)d_in[3];
    const float* o3 = (const float*)d_in[4];
    const float* t3 = (const float*)d_in[5];
    float* out = (float*)d_out;

    dim3 grid(BB, NPAIR);
    wnrmse_row_kernel<<<grid, ROW_THREADS>>>(o1, t1, o2, t2, o3, t3);
    wnrmse_reduce_kernel<<<1, RED_THREADS>>>(out);
}

// round 6
// speedup vs baseline: 1.0662x; 1.0009x over previous
#include <cuda_runtime.h>
#include <float.h>

#define BB 4096
#define NN 2048
#define NPAIR 3
#define ROW_THREADS 128          // 128 thr * 4 float4 = 512 float4 = one 2048-float row
#define RED_THREADS 1024

// Per-(pair,row) weighted contributions. Deterministic fixed-order final sum.
__device__ float g_partials[NPAIR * BB];

__global__ __launch_bounds__(ROW_THREADS)
void wnrmse_row_kernel(const float* __restrict__ o1, const float* __restrict__ t1,
                       const float* __restrict__ o2, const float* __restrict__ t2,
                       const float* __restrict__ o3, const float* __restrict__ t3) {
    const int b = blockIdx.x;   // batch row
    const int p = blockIdx.y;   // pair index
    const int tid = threadIdx.x;

    const float* o = (p == 0) ? o1 : ((p == 1) ? o2 : o3);
    const float* t = (p == 0) ? t1 : ((p == 1) ? t2 : t3);

    const float4* __restrict__ o4 = reinterpret_cast<const float4*>(o + (size_t)b * NN);
    const float4* __restrict__ t4 = reinterpret_cast<const float4*>(t + (size_t)b * NN);

    // 8 front-batched LDG.128 per thread (MLP_p1 = 8), all 128B-coalesced.
    float4 ov0 = o4[tid];
    float4 ov1 = o4[tid + ROW_THREADS];
    float4 ov2 = o4[tid + 2 * ROW_THREADS];
    float4 ov3 = o4[tid + 3 * ROW_THREADS];
    float4 tv0 = t4[tid];
    float4 tv1 = t4[tid + ROW_THREADS];
    float4 tv2 = t4[tid + 2 * ROW_THREADS];
    float4 tv3 = t4[tid + 3 * ROW_THREADS];

    float ssq = 0.0f, tmax = -FLT_MAX, tmin = FLT_MAX;
    {
        float d;
        d = ov0.x - tv0.x; ssq = fmaf(d, d, ssq); tmax = fmaxf(tmax, tv0.x); tmin = fminf(tmin, tv0.x);
        d = ov0.y - tv0.y; ssq = fmaf(d, d, ssq); tmax = fmaxf(tmax, tv0.y); tmin = fminf(tmin, tv0.y);
        d = ov0.z - tv0.z; ssq = fmaf(d, d, ssq); tmax = fmaxf(tmax, tv0.z); tmin = fminf(tmin, tv0.z);
        d = ov0.w - tv0.w; ssq = fmaf(d, d, ssq); tmax = fmaxf(tmax, tv0.w); tmin = fminf(tmin, tv0.w);
        d = ov1.x - tv1.x; ssq = fmaf(d, d, ssq); tmax = fmaxf(tmax, tv1.x); tmin = fminf(tmin, tv1.x);
        d = ov1.y - tv1.y; ssq = fmaf(d, d, ssq); tmax = fmaxf(tmax, tv1.y); tmin = fminf(tmin, tv1.y);
        d = ov1.z - tv1.z; ssq = fmaf(d, d, ssq); tmax = fmaxf(tmax, tv1.z); tmin = fminf(tmin, tv1.z);
        d = ov1.w - tv1.w; ssq = fmaf(d, d, ssq); tmax = fmaxf(tmax, tv1.w); tmin = fminf(tmin, tv1.w);
        d = ov2.x - tv2.x; ssq = fmaf(d, d, ssq); tmax = fmaxf(tmax, tv2.x); tmin = fminf(tmin, tv2.x);
        d = ov2.y - tv2.y; ssq = fmaf(d, d, ssq); tmax = fmaxf(tmax, tv2.y); tmin = fminf(tmin, tv2.y);
        d = ov2.z - tv2.z; ssq = fmaf(d, d, ssq); tmax = fmaxf(tmax, tv2.z); tmin = fminf(tmin, tv2.z);
        d = ov2.w - tv2.w; ssq = fmaf(d, d, ssq); tmax = fmaxf(tmax, tv2.w); tmin = fminf(tmin, tv2.w);
        d = ov3.x - tv3.x; ssq = fmaf(d, d, ssq); tmax = fmaxf(tmax, tv3.x); tmin = fminf(tmin, tv3.x);
        d = ov3.y - tv3.y; ssq = fmaf(d, d, ssq); tmax = fmaxf(tmax, tv3.y); tmin = fminf(tmin, tv3.y);
        d = ov3.z - tv3.z; ssq = fmaf(d, d, ssq); tmax = fmaxf(tmax, tv3.z); tmin = fminf(tmin, tv3.z);
        d = ov3.w - tv3.w; ssq = fmaf(d, d, ssq); tmax = fmaxf(tmax, tv3.w); tmin = fminf(tmin, tv3.w);
    }

    // Intra-warp reduce
    #pragma unroll
    for (int s = 16; s > 0; s >>= 1) {
        ssq  += __shfl_xor_sync(0xFFFFFFFFu, ssq,  s);
        tmax  = fmaxf(tmax, __shfl_xor_sync(0xFFFFFFFFu, tmax, s));
        tmin  = fminf(tmin, __shfl_xor_sync(0xFFFFFFFFu, tmin, s));
    }

    // Cross-warp reduce (4 warps)
    __shared__ float s_ssq[4], s_max[4], s_min[4];
    const int w = tid >> 5, l = tid & 31;
    if (l == 0) { s_ssq[w] = ssq; s_max[w] = tmax; s_min[w] = tmin; }
    __syncthreads();

    if (tid == 0) {
        float a  = (s_ssq[0] + s_ssq[1]) + (s_ssq[2] + s_ssq[3]);
        float mx = fmaxf(fmaxf(s_max[0], s_max[1]), fmaxf(s_max[2], s_max[3]));
        float mn = fminf(fminf(s_min[0], s_min[1]), fminf(s_min[2], s_min[3]));
        const float wgt = (p == 0) ? 0.5f : 0.25f;
        g_partials[p * BB + b] = wgt * sqrtf(a * (1.0f / NN)) / (mx - mn);
    }
}

// Tail: launched with PDL; overlaps its launch/prologue with the primary's drain.
__global__ __launch_bounds__(RED_THREADS)
void wnrmse_reduce_kernel(float* __restrict__ out) {
    // Wait until the primary grid's memory is visible.
    cudaGridDependencySynchronize();

    const int tid = threadIdx.x;
    const float4* __restrict__ p4 = reinterpret_cast<const float4*>(g_partials);

    float4 v0 = p4[tid];
    float4 v1 = p4[tid + RED_THREADS];
    float4 v2 = p4[tid + 2 * RED_THREADS];

    float s = ((v0.x + v0.y) + (v0.z + v0.w))
            + ((v1.x + v1.y) + (v1.z + v1.w))
            + ((v2.x + v2.y) + (v2.z + v2.w));

    #pragma unroll
    for (int sh = 16; sh > 0; sh >>= 1)
        s += __shfl_xor_sync(0xFFFFFFFFu, s, sh);

    __shared__ float s_part[32];
    const int w = tid >> 5, l = tid & 31;
    if (l == 0) s_part[w] = s;
    __syncthreads();
    if (w == 0) {
        float a = s_part[l];   // exactly 32 warps
        #pragma unroll
        for (int sh = 16; sh > 0; sh >>= 1)
            a += __shfl_xor_sync(0xFFFFFFFFu, a, sh);
        if (l == 0) out[0] = a * (1.0f / BB);
    }
}

extern "C" void kernel_launch(void* const* d_in, const int* in_sizes, int n_in,
                              void* d_out, int out_size) {
    const float* o1 = (const float*)d_in[0];
    const float* t1 = (const float*)d_in[1];
    const float* o2 = (const float*)d_in[2];
    const float* t2 = (const float*)d_in[3];
    const float* o3 = (const float*)d_in[4];
    const float* t3 = (const float*)d_in[5];
    float* out = (float*)d_out;

    dim3 grid(BB, NPAIR);
    wnrmse_row_kernel<<<grid, ROW_THREADS>>>(o1, t1, o2, t2, o3, t3);

    // Reduce kernel with programmatic dependent launch (overlap with primary drain).
    cudaLaunchConfig_t cfg = {};
    cfg.gridDim = dim3(1, 1, 1);
    cfg.blockDim = dim3(RED_THREADS, 1, 1);
    cfg.dynamicSmemBytes = 0;
    cfg.stream = 0;
    cudaLaunchAttribute attrs[1];
    attrs[0].id = cudaLaunchAttributeProgrammaticStreamSerialization;
    attrs[0].val.programmaticStreamSerializationAllowed = 1;
    cfg.attrs = attrs;
    cfg.numAttrs = 1;
    cudaLaunchKernelEx(&cfg, wnrmse_reduce_kernel, out);
}